// round 15
// baseline (speedup 1.0000x reference)
#include <cuda_runtime.h>
#include <math.h>

#define NPTS 15000
#define MP   1024
#define CS   512
#define MAXK 11000
#define BM 128
#define BN 64
#define BK 16

// ---------------- device-global scratch (allocation-free rule) ----------------
__device__ int    g_flag;
__device__ int    g_fps[2*MP];
__device__ float  g_xyzg[2*MP*4];
__device__ float  g_featg[2*CS*MP];        // [b][c][m]
__device__ float  g_featgT[2*MP*CS];       // [b*1024+m][c]
__device__ float  g_W1pT[4*528*256];       // [s][k][m]  k: 512 feat, 3 geo, pad
__device__ float  g_W2T [4*256*512];       // [s][k][m]
__device__ float  g_gWT [512*512];         // [k][m]
__device__ float  g_fWT [2048*512];        // [k][m]
__device__ int    g_colidx[294912];
__device__ float4 g_colgeo[294912];
__device__ float  g_H1[33554432];          // [256][Ncols_s], reused per scale
__device__ float  g_vpcat[2*2048*MP];      // [b][2048][m]
__device__ float  g_gatez[512*2048];       // [m_out][col]

// ---------------- mask dtype detection ----------------
__global__ void detect_mask(const unsigned* __restrict__ m) {
    int ok_i = 1, ok_f = 1;
    for (int i = threadIdx.x; i < 2048; i += blockDim.x) {
        unsigned v = m[i];
        if (!(v == 0u || v == 1u)) ok_i = 0;
        if (!(v == 0u || v == 0x3F800000u)) ok_f = 0;
    }
    int ai = __syncthreads_and(ok_i);
    int af = __syncthreads_and(ok_f);
    if (threadIdx.x == 0) g_flag = ai ? 0 : (af ? 2 : 1);
}

// ---------------- weight prep: permute + transpose ----------------
__global__ void prep_weights(const float* __restrict__ w1, const float* __restrict__ w2,
                             const float* __restrict__ gw, const float* __restrict__ fw) {
    int i = blockIdx.x * blockDim.x + threadIdx.x;
    if (i < 540672) {                       // W1pT [4][528][256]
        int s = i / 135168, r = i % 135168;
        int k = r >> 8, m = r & 255;
        float v = 0.f;
        if (k < 512)      v = w1[(s*256 + m)*515 + 3 + k];
        else if (k < 515) v = w1[(s*256 + m)*515 + (k - 512)];
        g_W1pT[i] = v; return;
    }
    i -= 540672;
    if (i < 524288) {                       // W2T [4][256][512]
        int s = i / 131072, r = i % 131072;
        int k = r >> 9, m = r & 511;
        g_W2T[i] = w2[(s*512 + m)*256 + k]; return;
    }
    i -= 524288;
    if (i < 262144) { int k = i >> 9, m = i & 511; g_gWT[i] = gw[m*512 + k]; return; }
    i -= 262144;
    if (i < 1048576){ int k = i >> 9, m = i & 511; g_fWT[i] = fw[m*2048 + k]; }
}

// ---------------- masked FPS (bit-exact replication) ----------------
__global__ __launch_bounds__(1024)
void fps_kernel(const float* __restrict__ xyz, const void* __restrict__ mask) {
    extern __shared__ float sm[];
    float* sx = sm;            float* sy = sm + MAXK;  float* sz = sm + 2*MAXK;
    float* dist = sm + 3*MAXK; int* sidx = (int*)(sm + 4*MAXK);
    __shared__ int warpcnt[32], warpoff[32], sTot, sCnt, sFar;
    __shared__ unsigned long long wred[32];
    const int b = blockIdx.x, tid = threadIdx.x, lane = tid & 31, w = tid >> 5;
    const int flag = g_flag;
    if (tid == 0) sCnt = 0;
    __syncthreads();
    // ordered compaction of masked points
    for (int base = 0; base < NPTS; base += 1024) {
        int i = base + tid; bool v = false;
        if (i < NPTS) {
            if (flag == 0)      v = ((const int*)mask)[b*NPTS + i] != 0;
            else if (flag == 1) v = ((const unsigned char*)mask)[b*NPTS + i] != 0;
            else                v = ((const float*)mask)[b*NPTS + i] != 0.f;
        }
        unsigned bal = __ballot_sync(~0u, v);
        if (lane == 0) warpcnt[w] = __popc(bal);
        __syncthreads();
        if (tid < 32) {
            int c = warpcnt[tid], x = c;
            for (int o = 1; o < 32; o <<= 1) { int y = __shfl_up_sync(~0u, x, o); if (tid >= o) x += y; }
            warpoff[tid] = x - c; if (tid == 31) sTot = x;
        }
        __syncthreads();
        if (v) {
            int slot = sCnt + warpoff[w] + __popc(bal & ((1u << lane) - 1));
            if (slot < MAXK) {
                const float* p = xyz + ((size_t)b*NPTS + i)*3;
                sx[slot] = p[0]; sy[slot] = p[1]; sz[slot] = p[2]; sidx[slot] = i;
            }
        }
        __syncthreads();
        if (tid == 0) sCnt += sTot;
        __syncthreads();
    }
    int K = sCnt; if (K > MAXK) K = MAXK;
    for (int t = tid; t < K; t += 1024) dist[t] = 1e10f;
    __syncthreads();
    int far = 0;
    for (int it = 0; it < MP; it++) {
        if (tid == 0) g_fps[b*MP + it] = sidx[far];
        float fx = sx[far], fy = sy[far], fz = sz[far];
        unsigned long long lm = 0ull;
        for (int t = tid; t < K; t += 1024) {
            float dx = __fadd_rn(sx[t], -fx);
            float dy = __fadd_rn(sy[t], -fy);
            float dz = __fadd_rn(sz[t], -fz);
            float d  = __fadd_rn(__fadd_rn(__fmul_rn(dx,dx), __fmul_rn(dy,dy)), __fmul_rn(dz,dz));
            float nd = fminf(dist[t], d); dist[t] = nd;
            unsigned long long key = ((unsigned long long)__float_as_uint(nd) << 32)
                                   | (unsigned long long)(0xFFFFFFFFu - (unsigned)t);
            if (key > lm) lm = key;
        }
        for (int o = 16; o; o >>= 1) { unsigned long long ot = __shfl_down_sync(~0u, lm, o); if (ot > lm) lm = ot; }
        if (lane == 0) wred[w] = lm;
        __syncthreads();
        if (tid < 32) {
            unsigned long long m2 = wred[tid];
            for (int o = 16; o; o >>= 1) { unsigned long long ot = __shfl_down_sync(~0u, m2, o); if (ot > m2) m2 = ot; }
            if (tid == 0) sFar = (int)(0xFFFFFFFFu - (unsigned)(m2 & 0xFFFFFFFFu));
        }
        __syncthreads();
        far = sFar;
    }
}

// ---------------- gathers ----------------
__global__ void gather_xyz(const float* __restrict__ xyz) {
    int t = blockIdx.x * blockDim.x + threadIdx.x;
    if (t >= 2*MP) return;
    int b = t >> 10, idx = g_fps[t];
    const float* p = xyz + ((size_t)b*NPTS + idx)*3;
    g_xyzg[t*4+0] = p[0]; g_xyzg[t*4+1] = p[1]; g_xyzg[t*4+2] = p[2]; g_xyzg[t*4+3] = 0.f;
}

__global__ void gather_feat(const float* __restrict__ sf) {
    int t = blockIdx.x;                 // b*1024+m
    int b = t >> 10, m = t & 1023;
    int idx = g_fps[t];
    const float* src = sf + (size_t)b*CS*NPTS + idx;
    for (int c = threadIdx.x; c < CS; c += blockDim.x) {
        float v = src[(size_t)c*NPTS];
        g_featgT[(size_t)t*CS + c] = v;
        g_featg[((size_t)b*CS + c)*MP + m] = v;
    }
}

// ---------------- local frames + per-scale neighbor lists ----------------
__global__ __launch_bounds__(1024)
void build_kernel(const float* __restrict__ vrot, float4 rad2) {
    const int bj = blockIdx.x, b = bj >> 10;
    const int k = threadIdx.x, lane = k & 31, w = k >> 5;
    __shared__ float sR[9], sC[3], sFG[3];
    __shared__ int warpcnt[32], warpoff[32], sCount, sFirstK;
    if (k < 9) sR[k] = vrot[(size_t)bj*9 + k];
    if (k < 3) sC[k] = g_xyzg[(size_t)bj*4 + k];
    __syncthreads();
    size_t pk = ((size_t)(b*MP + k))*4;
    float rx = __fadd_rn(g_xyzg[pk+0], -sC[0]);
    float ry = __fadd_rn(g_xyzg[pk+1], -sC[1]);
    float rz = __fadd_rn(g_xyzg[pk+2], -sC[2]);
    float l0 = rx*sR[0] + ry*sR[3] + rz*sR[6];
    float l1 = rx*sR[1] + ry*sR[4] + rz*sR[7];
    float l2 = rx*sR[2] + ry*sR[5] + rz*sR[8];
    bool inh = (l0 >= -0.02f) && (l0 <= 0.06f);
    float r2 = l1*l1 + l2*l2;
    float radA[4] = {rad2.x, rad2.y, rad2.z, rad2.w};
    int   nsA [4] = {16, 32, 32, 64};
    long  coA [4] = {0, 32768, 98304, 163840};
    for (int s = 0; s < 4; s++) {
        bool v = inh && (r2 < radA[s]);
        unsigned bal = __ballot_sync(~0u, v);
        if (lane == 0) warpcnt[w] = __popc(bal);
        __syncthreads();
        if (k < 32) {
            int c = warpcnt[k], x = c;
            for (int o = 1; o < 32; o <<= 1) { int y = __shfl_up_sync(~0u, x, o); if (k >= o) x += y; }
            warpoff[k] = x - c; if (k == 31) sCount = x;
        }
        __syncthreads();
        int ns = nsA[s];
        long basep = coA[s] + (long)bj * ns;
        if (v) {
            int rank = warpoff[w] + __popc(bal & ((1u << lane) - 1));
            if (rank == 0) { sFirstK = k; sFG[0] = l0; sFG[1] = l1; sFG[2] = l2; }
            if (rank < ns) {
                g_colidx[basep + rank] = b*MP + k;
                g_colgeo[basep + rank] = make_float4(l0, l1, l2, 0.f);
            }
        }
        __syncthreads();
        int cnt = sCount < ns ? sCount : ns;
        if (k >= cnt && k < ns) {
            g_colidx[basep + k] = b*MP + sFirstK;
            g_colgeo[basep + k] = make_float4(sFG[0], sFG[1], sFG[2], 0.f);
        }
    }
}

// ---------------- fused SGEMM, 4 modes ----------------
// C = A_T(K x MT) * B(K x N); MODE0: crop L1 (gathered B, relu -> H1)
// MODE1: crop L2 (B=H1, relu + group-max -> vpcat)
// MODE2: gate_w @ feat_g + b -> gatez
// MODE3: fuse_w @ vpcat + b + sigmoid(gatez)*feat_g -> out
template<int MODE>
__global__ __launch_bounds__(256, 2)
void gemm(const float* __restrict__ bias, float* __restrict__ outp,
          int s, int Ncols, int ns, int cOff)
{
    constexpr int K  = MODE==0 ? 528 : MODE==1 ? 256 : MODE==2 ? 512 : 2048;
    constexpr int MT = MODE==0 ? 256 : 512;
    __shared__ float As[BK][BM];
    __shared__ float Bs[BK][BN];
    const int tid = threadIdx.x, tx = tid & 15, ty = tid >> 4;
    const int mBase = blockIdx.y * BM, nBase = blockIdx.x * BN;
    const float* A = MODE==0 ? g_W1pT + s*528*256 :
                     MODE==1 ? g_W2T  + s*256*512 :
                     MODE==2 ? g_gWT  : g_fWT;
    float acc[8][4];
    #pragma unroll
    for (int i = 0; i < 8; i++)
        #pragma unroll
        for (int j = 0; j < 4; j++) acc[i][j] = 0.f;

    const float* Bp = nullptr; int ldB = MP;
    if (MODE == 1) { Bp = g_H1 + nBase; ldB = Ncols; }
    else if (MODE == 2) Bp = g_featg + (size_t)(nBase >> 10)*CS*MP   + (nBase & 1023);
    else if (MODE == 3) Bp = g_vpcat + (size_t)(nBase >> 10)*2048*MP + (nBase & 1023);

    int colA = 0; float4 geo4 = make_float4(0,0,0,0);
    const int bn = tid & 63, bq = tid >> 6;
    if (MODE == 0) {
        int c = cOff + nBase + bn;
        colA = g_colidx[c];
        geo4 = g_colgeo[c];
    }

    for (int k0 = 0; k0 < K; k0 += BK) {
        float4 a0 = *(const float4*)(A + (size_t)(k0 + ty)*MT + mBase + tx*8);
        float4 a1 = *(const float4*)(A + (size_t)(k0 + ty)*MT + mBase + tx*8 + 4);
        float4 bv;
        if (MODE == 0) {
            int kk = k0 + bq*4;
            if (kk + 3 < 512)   bv = *(const float4*)(g_featgT + (size_t)colA*CS + kk);
            else if (kk == 512) bv = make_float4(geo4.x, geo4.y, geo4.z, 0.f);
            else                bv = make_float4(0, 0, 0, 0);
        } else {
            bv = *(const float4*)(Bp + (size_t)(k0 + ty)*ldB + tx*4);
        }
        __syncthreads();
        *(float4*)&As[ty][tx*8]     = a0;
        *(float4*)&As[ty][tx*8 + 4] = a1;
        if (MODE == 0) {
            Bs[bq*4+0][bn] = bv.x; Bs[bq*4+1][bn] = bv.y;
            Bs[bq*4+2][bn] = bv.z; Bs[bq*4+3][bn] = bv.w;
        } else {
            *(float4*)&Bs[ty][tx*4] = bv;
        }
        __syncthreads();
        #pragma unroll
        for (int kk = 0; kk < BK; kk++) {
            float4 b4 = *(float4*)&Bs[kk][tx*4];
            float4 x0 = *(float4*)&As[kk][ty*8];
            float4 x1 = *(float4*)&As[kk][ty*8 + 4];
            float am[8] = {x0.x,x0.y,x0.z,x0.w,x1.x,x1.y,x1.z,x1.w};
            float bb[4] = {b4.x,b4.y,b4.z,b4.w};
            #pragma unroll
            for (int i = 0; i < 8; i++)
                #pragma unroll
                for (int j = 0; j < 4; j++) acc[i][j] += am[i]*bb[j];
        }
    }

    if (MODE == 0) {
        #pragma unroll
        for (int i = 0; i < 8; i++) {
            int m = mBase + ty*8 + i;
            float bb = bias[m];
            float4 v = make_float4(fmaxf(acc[i][0]+bb,0.f), fmaxf(acc[i][1]+bb,0.f),
                                   fmaxf(acc[i][2]+bb,0.f), fmaxf(acc[i][3]+bb,0.f));
            *(float4*)(g_H1 + (size_t)m*Ncols + nBase + tx*4) = v;
        }
    } else if (MODE == 1) {
        int gsz = ns >> 2;
        #pragma unroll
        for (int i = 0; i < 8; i++) {
            int m = mBase + ty*8 + i;
            float bb = bias[m];
            float lm = fmaxf(fmaxf(fmaxf(acc[i][0]+bb,0.f), fmaxf(acc[i][1]+bb,0.f)),
                             fmaxf(fmaxf(acc[i][2]+bb,0.f), fmaxf(acc[i][3]+bb,0.f)));
            for (int off = 1; off < gsz; off <<= 1)
                lm = fmaxf(lm, __shfl_xor_sync(~0u, lm, off));
            if ((tx & (gsz - 1)) == 0) {
                int g = (nBase + tx*4) / ns;
                g_vpcat[((size_t)((g >> 10)*2048 + s*512 + m))*MP + (g & 1023)] = lm;
            }
        }
    } else if (MODE == 2) {
        #pragma unroll
        for (int i = 0; i < 8; i++) {
            int m = mBase + ty*8 + i;
            float bb = bias[m];
            float4 v = make_float4(acc[i][0]+bb, acc[i][1]+bb, acc[i][2]+bb, acc[i][3]+bb);
            *(float4*)(g_gatez + (size_t)m*2048 + nBase + tx*4) = v;
        }
    } else {
        int c = nBase + tx*4, b = c >> 10, cj = c & 1023;
        #pragma unroll
        for (int i = 0; i < 8; i++) {
            int m = mBase + ty*8 + i;
            float bb = bias[m];
            float4 gz = *(float4*)(g_gatez + (size_t)m*2048 + c);
            float4 fg = *(float4*)(g_featg + (size_t)b*CS*MP + (size_t)m*MP + cj);
            float4 v;
            v.x = acc[i][0] + bb + fg.x / (1.f + expf(-gz.x));
            v.y = acc[i][1] + bb + fg.y / (1.f + expf(-gz.y));
            v.z = acc[i][2] + bb + fg.z / (1.f + expf(-gz.z));
            v.w = acc[i][3] + bb + fg.w / (1.f + expf(-gz.w));
            *(float4*)(outp + (size_t)b*CS*MP + (size_t)m*MP + cj) = v;
        }
    }
}

// ---------------- launch ----------------
extern "C" void kernel_launch(void* const* d_in, const int* in_sizes, int n_in,
                              void* d_out, int out_size) {
    const float* xyz  = (const float*)d_in[0];
    const float* sf   = (const float*)d_in[1];
    const void*  mask =               d_in[2];
    const float* vrot = (const float*)d_in[3];
    const float* w1   = (const float*)d_in[4];
    const float* b1   = (const float*)d_in[5];
    const float* w2   = (const float*)d_in[6];
    const float* b2   = (const float*)d_in[7];
    const float* fw   = (const float*)d_in[8];
    const float* fb   = (const float*)d_in[9];
    const float* gw   = (const float*)d_in[10];
    const float* gb   = (const float*)d_in[11];
    float* out = (float*)d_out;

    detect_mask<<<1, 256>>>((const unsigned*)mask);
    prep_weights<<<(2375680 + 255)/256, 256>>>(w1, w2, gw, fw);

    cudaFuncSetAttribute(fps_kernel, cudaFuncAttributeMaxDynamicSharedMemorySize, MAXK*5*4);
    fps_kernel<<<2, 1024, MAXK*5*4>>>(xyz, mask);

    gather_xyz<<<8, 256>>>(xyz);
    gather_feat<<<2048, 128>>>(sf);

    float4 rad2 = make_float4((float)(0.025*0.025), (float)(0.0375*0.0375),
                              (float)(0.05*0.05),   (float)(0.075*0.075));
    build_kernel<<<2048, 1024>>>(vrot, rad2);

    int nsA[4]  = {16, 32, 32, 64};
    int coff[4] = {0, 32768, 98304, 163840};
    for (int s = 0; s < 4; s++) {
        int Nc = 2048 * nsA[s];
        gemm<0><<<dim3(Nc/64, 2), 256>>>(b1 + s*256, nullptr, s, Nc, 0, coff[s]);
        gemm<1><<<dim3(Nc/64, 4), 256>>>(b2 + s*512, nullptr, s, Nc, nsA[s], 0);
    }
    gemm<2><<<dim3(32, 4), 256>>>(gb, nullptr, 0, 2048, 0, 0);
    gemm<3><<<dim3(32, 4), 256>>>(fb, out,     0, 2048, 0, 0);
}